// round 2
// baseline (speedup 1.0000x reference)
#include <cuda_runtime.h>
#include <cuda_bf16.h>

// ---------------------------------------------------------------------------
// Net_15762529976343: STN-style head.
//   f   = BN(conv3x3_s2(x, Wlast))                      [8,2048,5,5]
//   xs1 = relu(BN(conv3x3(f,  W1)))                     [8,2048,5,5]
//   xs2 = relu(BN(conv3x3(xs1,W2)))                     [8,2048,5,5]
//   h   = relu(conv3x3(xs2, fc1_w as [512,2048,3,3]))   [8,512,5,5]   (== per-patch fc1)
//   p   = fc2_w @ h          -> theta -> 9 grid pts per (b,pos)
//   samp= bilinear(f padded 7x7, grids)  -> im2col A directly
//   L   = GEMM(samp, conv_stn_w) + bias  -> joint softmax over 201*25
// All heavy work: 5 GEMMs with M=200, K=18432.
// ---------------------------------------------------------------------------

#define MM   200
#define KKT  18432
#define CCH  2048

// ---- scratch (no allocations allowed) ----
__device__ __align__(128) float g_A[MM * KKT];          // im2col buffer (14.75 MB)
__device__ __align__(128) float g_C[MM * CCH];          // raw conv output [m, c]
__device__ __align__(128) float g_f[MM * CCH];          // f,  layout [b][pos][c]
__device__ __align__(128) float g_xs[MM * CCH];         // xs1 then xs2
__device__ __align__(128) float g_h[MM * 512];          // fc1 raw (pre-relu)
__device__ __align__(128) float g_L[MM * 201];          // conv_stn logits [m, o]
__device__ __align__(128) float g_part[1 << 20];        // split-K partials
__device__ float g_mean[CCH], g_rstd[CCH];
__device__ float g_grids[8 * 225 * 2];

// ---------------------------------------------------------------------------
// im2col from x [8,2048,10,10], k=3 s=2 p=1  -> A[m][c*9+u*3+v]
// ---------------------------------------------------------------------------
__global__ void im2col_x_k(const float* __restrict__ x) {
    int t = blockIdx.x * 256 + threadIdx.x;
    if (t >= MM * CCH) return;
    int c = t & 2047, m = t >> 11;
    int b = m / 25, pos = m % 25;
    int oy = pos / 5, ox = pos % 5;
    const float* xb = x + ((long)(b * CCH + c)) * 100;
    float* ab = g_A + (long)m * KKT + c * 9;
#pragma unroll
    for (int u = 0; u < 3; u++) {
        int iy = 2 * oy - 1 + u;
#pragma unroll
        for (int v = 0; v < 3; v++) {
            int ix = 2 * ox - 1 + v;
            float val = (iy >= 0 && iy < 10 && ix >= 0 && ix < 10) ? xb[iy * 10 + ix] : 0.f;
            ab[u * 3 + v] = val;
        }
    }
}

// ---------------------------------------------------------------------------
// im2col from a 5x5 map (layout [b][pos][c]), k=3 s=1 p=1
// sel: 0 -> g_f, 1 -> g_xs
// ---------------------------------------------------------------------------
__global__ void im2col5_k(int sel) {
    int t = blockIdx.x * 256 + threadIdx.x;
    if (t >= MM * CCH) return;
    int c = t & 2047, m = t >> 11;
    int b = m / 25, pos = m % 25;
    int oy = pos / 5, ox = pos % 5;
    const float* src = sel ? g_xs : g_f;
    float* ab = g_A + (long)m * KKT + c * 9;
#pragma unroll
    for (int u = 0; u < 3; u++) {
        int iy = oy - 1 + u;
#pragma unroll
        for (int v = 0; v < 3; v++) {
            int ix = ox - 1 + v;
            float val = (iy >= 0 && iy < 5 && ix >= 0 && ix < 5)
                        ? src[(b * 25 + iy * 5 + ix) * CCH + c] : 0.f;
            ab[u * 3 + v] = val;
        }
    }
}

// ---------------------------------------------------------------------------
// SGEMM: C[m,n] = sum_k A[m,k] * Bw[n,k];  A = g_A (M=200, K=18432)
// BM=BN=64, BK=16, 256 threads, 4x4 microtile. grid=(ceil(N/64), 4, splitk)
// toPart: 0 -> write g_C (splitk must be 1), 1 -> g_part[z][m][n]
// ---------------------------------------------------------------------------
__global__ void __launch_bounds__(256) sgemm_k(const float* __restrict__ Bw,
                                               int N, int klen, int toPart) {
    __shared__ float As[16][64];
    __shared__ float Bs[16][68];
    int tid = threadIdx.x;
    int tx = tid & 15, ty = tid >> 4;
    int n0 = blockIdx.x * 64;
    int m0 = blockIdx.y * 64;
    int z  = blockIdx.z;
    int k0 = z * klen;
    int kend = k0 + klen;
    int lr = tid >> 2;            // 0..63
    int lc = (tid & 3) << 2;      // 0,4,8,12

    float acc[4][4];
#pragma unroll
    for (int i = 0; i < 4; i++)
#pragma unroll
        for (int j = 0; j < 4; j++) acc[i][j] = 0.f;

    for (int kb = k0; kb < kend; kb += 16) {
        float4 av = make_float4(0.f, 0.f, 0.f, 0.f);
        float4 bv = make_float4(0.f, 0.f, 0.f, 0.f);
        int gm = m0 + lr;
        if (gm < MM) av = *(const float4*)(g_A + (long)gm * KKT + kb + lc);
        int gn = n0 + lr;
        if (gn < N)  bv = *(const float4*)(Bw + (long)gn * KKT + kb + lc);
        As[lc + 0][lr] = av.x; As[lc + 1][lr] = av.y;
        As[lc + 2][lr] = av.z; As[lc + 3][lr] = av.w;
        Bs[lc + 0][lr] = bv.x; Bs[lc + 1][lr] = bv.y;
        Bs[lc + 2][lr] = bv.z; Bs[lc + 3][lr] = bv.w;
        __syncthreads();
#pragma unroll
        for (int kk = 0; kk < 16; kk++) {
            float4 a4 = *(const float4*)&As[kk][ty << 2];
            float4 b4 = *(const float4*)&Bs[kk][tx << 2];
            float ar[4] = {a4.x, a4.y, a4.z, a4.w};
            float br[4] = {b4.x, b4.y, b4.z, b4.w};
#pragma unroll
            for (int i = 0; i < 4; i++)
#pragma unroll
                for (int j = 0; j < 4; j++) acc[i][j] += ar[i] * br[j];
        }
        __syncthreads();
    }

    float* Cd = toPart ? (g_part + (long)z * MM * N) : g_C;
#pragma unroll
    for (int i = 0; i < 4; i++) {
        int m = m0 + (ty << 2) + i;
        if (m >= MM) continue;
#pragma unroll
        for (int j = 0; j < 4; j++) {
            int n = n0 + (tx << 2) + j;
            if (n < N) Cd[(long)m * N + n] = acc[i][j];
        }
    }
}

// ---------------------------------------------------------------------------
// split-K reduction: dst_sel 1 -> g_h, 2 -> g_L
// ---------------------------------------------------------------------------
__global__ void reduce_k(int dst_sel, int N, int nz) {
    int i = blockIdx.x * 256 + threadIdx.x;
    int tot = MM * N;
    if (i >= tot) return;
    float s = 0.f;
    for (int zz = 0; zz < nz; zz++) s += g_part[(long)zz * tot + i];
    float* dst = (dst_sel == 1) ? g_h : g_L;
    dst[i] = s;
}

// ---------------------------------------------------------------------------
// BN batch statistics over m (200 samples) per channel n (of g_C)
// ---------------------------------------------------------------------------
__global__ void bn_stats_k() {
    __shared__ float ss[2], ss2[2];
    int n = blockIdx.x, tid = threadIdx.x;
    float s = 0.f, s2 = 0.f;
    for (int m = tid; m < MM; m += 64) {
        float v = g_C[(long)m * CCH + n];
        s += v; s2 += v * v;
    }
#pragma unroll
    for (int o = 16; o > 0; o >>= 1) {
        s  += __shfl_xor_sync(0xffffffffu, s,  o);
        s2 += __shfl_xor_sync(0xffffffffu, s2, o);
    }
    if ((tid & 31) == 0) { ss[tid >> 5] = s; ss2[tid >> 5] = s2; }
    __syncthreads();
    if (tid == 0) {
        float S = ss[0] + ss[1], S2 = ss2[0] + ss2[1];
        float mean = S * (1.f / 200.f);
        float var  = S2 * (1.f / 200.f) - mean * mean;
        g_mean[n] = mean;
        g_rstd[n] = rsqrtf(var + 1e-5f);
    }
}

// dst_sel: 0 -> g_f, 1 -> g_xs
__global__ void bn_apply_k(const float* __restrict__ gam, const float* __restrict__ bet,
                           int dst_sel, int relu) {
    int i = blockIdx.x * 256 + threadIdx.x;
    if (i >= MM * CCH) return;
    int n = i & 2047;
    float v = (g_C[i] - g_mean[n]) * g_rstd[n] * gam[n] + bet[n];
    if (relu) v = fmaxf(v, 0.f);
    float* dst = dst_sel ? g_xs : g_f;
    dst[i] = v;
}

// ---------------------------------------------------------------------------
// fc2 (4x512) per (b,pos) on relu(g_h); theta -> output; 9 grid pts -> g_grids
// ---------------------------------------------------------------------------
__global__ void fc2_theta_k(const float* __restrict__ fc2_w, float* __restrict__ out_theta) {
    int m = blockIdx.x;       // b*25 + pos
    int tid = threadIdx.x;    // 128
    __shared__ float sh[512];
    __shared__ float sp[4];
    for (int i = tid; i < 512; i += 128) sh[i] = fmaxf(g_h[m * 512 + i], 0.f);
    __syncthreads();
    int w = tid >> 5, lane = tid & 31;
    float s = 0.f;
    for (int j = lane; j < 512; j += 32) s += sh[j] * fc2_w[w * 512 + j];
#pragma unroll
    for (int o = 16; o > 0; o >>= 1) s += __shfl_xor_sync(0xffffffffu, s, o);
    if (lane == 0) sp[w] = s;
    __syncthreads();
    if (tid == 0) {
        float p0 = sp[0], p1 = sp[1], p2 = sp[2], p3 = sp[3];
        float th[6] = {1.f + p0, 0.f, p1, 0.f, 1.f + p2, p3};
#pragma unroll
        for (int t = 0; t < 6; t++) out_theta[m * 6 + t] = th[t];
        int pi = (m % 25) / 5, pj = (m % 25) % 5;
#pragma unroll
        for (int u = 0; u < 3; u++)
#pragma unroll
            for (int v = 0; v < 3; v++) {
                float lx = (float)(pj + v) * (1.f / 3.f) - 1.f;
                float ly = (float)(pi + u) * (1.f / 3.f) - 1.f;
                int pt = m * 9 + u * 3 + v;
                g_grids[pt * 2 + 0] = (1.f + p0) * lx + p1;
                g_grids[pt * 2 + 1] = (1.f + p2) * ly + p3;
            }
    }
}

// ---------------------------------------------------------------------------
// bilinear sample of f padded to 7x7 (zero ring), align_corners=True.
// writes directly into im2col A layout: A[m][c*9 + k]
// one block per sample point (1800 points), threads over channels.
// ---------------------------------------------------------------------------
__global__ void sample_k(void) {
    int pt = blockIdx.x;          // 0..1799 : m*9 + k
    int m = pt / 9, k = pt % 9;
    int b = m / 25;
    float gx = (g_grids[pt * 2 + 0] + 1.f) * 3.f;   // (x+1)*0.5*(7-1)
    float gy = (g_grids[pt * 2 + 1] + 1.f) * 3.f;
    float x0f = floorf(gx), y0f = floorf(gy);
    int   x0i = (int)x0f,  y0i = (int)y0f;
    float wx1 = gx - x0f, wx0 = 1.f - wx1;
    float wy1 = gy - y0f, wy0 = 1.f - wy1;
    int   cx[2] = {x0i, x0i + 1}, cy[2] = {y0i, y0i + 1};
    float wxx[2] = {wx0, wx1},    wyy[2] = {wy0, wy1};
    float wgt[4];
    int   off[4];
#pragma unroll
    for (int a = 0; a < 2; a++)
#pragma unroll
        for (int c2 = 0; c2 < 2; c2++) {
            int xi = cx[c2], yi = cy[a];
            // nonzero only in the interior (padding ring of f_p is zero)
            bool val = (xi >= 1 && xi <= 5 && yi >= 1 && yi <= 5);
            wgt[a * 2 + c2] = val ? wyy[a] * wxx[c2] : 0.f;
            off[a * 2 + c2] = val ? ((b * 25 + (yi - 1) * 5 + (xi - 1)) * CCH) : 0;
        }
    float* ab = g_A + (long)m * KKT + k;
    for (int c = threadIdx.x; c < CCH; c += blockDim.x) {
        float v = wgt[0] * g_f[off[0] + c] + wgt[1] * g_f[off[1] + c]
                + wgt[2] * g_f[off[2] + c] + wgt[3] * g_f[off[3] + c];
        ab[(long)c * 9] = v;
    }
}

// ---------------------------------------------------------------------------
// joint softmax over 201*25 per batch; writes classif [8,201] and s [8,201,25]
// ---------------------------------------------------------------------------
__global__ void softmax_k(const float* __restrict__ bias, float* __restrict__ out) {
    int b = blockIdx.x;
    int tid = threadIdx.x;            // 512
    __shared__ float sm[5025];
    __shared__ float red[512];
    float lmax = -3.0e38f;
    for (int idx = tid; idx < 5025; idx += 512) {
        int o = idx / 25, pos = idx % 25;
        float v = g_L[(b * 25 + pos) * 201 + o] + bias[o];
        sm[idx] = v;
        lmax = fmaxf(lmax, v);
    }
    red[tid] = lmax;
    __syncthreads();
    for (int s = 256; s > 0; s >>= 1) {
        if (tid < s) red[tid] = fmaxf(red[tid], red[tid + s]);
        __syncthreads();
    }
    float mx = red[0];
    __syncthreads();
    float lsum = 0.f;
    for (int idx = tid; idx < 5025; idx += 512) {
        float e = expf(sm[idx] - mx);
        sm[idx] = e;
        lsum += e;
    }
    red[tid] = lsum;
    __syncthreads();
    for (int s = 256; s > 0; s >>= 1) {
        if (tid < s) red[tid] += red[tid + s];
        __syncthreads();
    }
    float inv = 1.f / red[0];
    __syncthreads();
    float* s_out = out + 1608;                 // after classif [8,201]
    for (int idx = tid; idx < 5025; idx += 512)
        s_out[b * 5025 + idx] = sm[idx] * inv; // idx = o*25 + pos matches [201,5,5]
    for (int o = tid; o < 201; o += 512) {
        float acc = 0.f;
        for (int pos = 0; pos < 25; pos++) acc += sm[o * 25 + pos];
        out[b * 201 + o] = acc * inv;
    }
}

// ---------------------------------------------------------------------------
extern "C" void kernel_launch(void* const* d_in, const int* in_sizes, int n_in,
                              void* d_out, int out_size) {
    const float* x           = (const float*)d_in[0];
    // d_in[1]=epoch, d_in[2]=flag (unused)
    const float* conv_last_w = (const float*)d_in[3];
    const float* bn_last_g   = (const float*)d_in[4];
    const float* bn_last_b   = (const float*)d_in[5];
    const float* loc_w1      = (const float*)d_in[6];
    const float* loc_g1      = (const float*)d_in[7];
    const float* loc_b1      = (const float*)d_in[8];
    const float* loc_w2      = (const float*)d_in[9];
    const float* loc_g2      = (const float*)d_in[10];
    const float* loc_b2      = (const float*)d_in[11];
    const float* fc1_w       = (const float*)d_in[12];
    const float* fc2_w       = (const float*)d_in[13];
    const float* conv_stn_w  = (const float*)d_in[14];
    const float* conv_stn_b  = (const float*)d_in[15];
    float* out = (float*)d_out;
    float* out_theta = out + 1608 + 40200;     // classif(1608) + s(40200)

    const int ELT_BLOCKS = (MM * CCH + 255) / 256;   // 1600

    // ---- backbone tail: conv_last + BN -> f ----
    im2col_x_k<<<ELT_BLOCKS, 256>>>(x);
    sgemm_k<<<dim3(32, 4, 1), 256>>>(conv_last_w, 2048, KKT, 0);
    bn_stats_k<<<2048, 64>>>();
    bn_apply_k<<<ELT_BLOCKS, 256>>>(bn_last_g, bn_last_b, 0, 0);

    // ---- localization conv1 ----
    im2col5_k<<<ELT_BLOCKS, 256>>>(0);
    sgemm_k<<<dim3(32, 4, 1), 256>>>(loc_w1, 2048, KKT, 0);
    bn_stats_k<<<2048, 64>>>();
    bn_apply_k<<<ELT_BLOCKS, 256>>>(loc_g1, loc_b1, 1, 1);

    // ---- localization conv2 ----
    im2col5_k<<<ELT_BLOCKS, 256>>>(1);
    sgemm_k<<<dim3(32, 4, 1), 256>>>(loc_w2, 2048, KKT, 0);
    bn_stats_k<<<2048, 64>>>();
    bn_apply_k<<<ELT_BLOCKS, 256>>>(loc_g2, loc_b2, 1, 1);

    // ---- fc1 (== 3x3 conv with 512 outputs), split-K=4 ----
    im2col5_k<<<ELT_BLOCKS, 256>>>(1);
    sgemm_k<<<dim3(8, 4, 4), 256>>>(fc1_w, 512, KKT / 4, 1);
    reduce_k<<<(MM * 512 + 255) / 256, 256>>>(1, 512, 4);

    // ---- fc2 + theta + grids ----
    fc2_theta_k<<<200, 128>>>(fc2_w, out_theta);

    // ---- bilinear sample -> im2col A ----
    sample_k<<<1800, 256>>>();

    // ---- conv_stn GEMM, split-K=8 ----
    sgemm_k<<<dim3(4, 4, 8), 256>>>(conv_stn_w, 201, KKT / 8, 1);
    reduce_k<<<(MM * 201 + 255) / 256, 256>>>(2, 201, 8);

    // ---- joint softmax + outputs ----
    softmax_k<<<8, 512>>>(conv_stn_b, out);
}

// round 7
// speedup vs baseline: 4.3939x; 4.3939x over previous
#include <cuda_runtime.h>
#include <cuda_bf16.h>
#include <cstdint>

// ---------------------------------------------------------------------------
// Net_15762529976343 — STN head. 5 GEMMs (M=200, K=18432) on tensor cores.
// Dual path: tcgen05 (only when compiling for sm_103a) else mma.sync bf16.
// Both use bf16 hi/lo 3-term fp32 emulation with fp32 accumulation.
// ---------------------------------------------------------------------------

#if defined(__CUDA_ARCH__) && defined(__CUDA_ARCH_FEAT_SM103_ALL)
#define HAS_TCGEN05 1
#else
#define HAS_TCGEN05 0
#endif

#define MM   200
#define KKT  18432
#define CCH  2048

// ---- scratch ----
__device__ __align__(128) float g_A[MM * KKT];
__device__ __align__(128) float g_C[MM * CCH];
__device__ __align__(128) float g_f[MM * CCH];
__device__ __align__(128) float g_xs[MM * CCH];
__device__ __align__(128) float g_h[MM * 512];
__device__ __align__(128) float g_L[MM * 201];
__device__ __align__(128) float g_part[3276800];      // up to 8*200*2048 fp32
__device__ float g_mean[CCH], g_rstd[CCH];
__device__ float g_grids[8 * 225 * 2];

// ---------------------------------------------------------------------------
// helpers
// ---------------------------------------------------------------------------
__device__ __forceinline__ uint32_t smem_u32(const void* p) {
    uint32_t a;
    asm("{ .reg .u64 t; cvta.to.shared.u64 t, %1; cvt.u32.u64 %0, t; }"
        : "=r"(a) : "l"(p));
    return a;
}
__device__ __forceinline__ uint32_t swz(uint32_t off) {
    return off ^ ((off >> 3) & 0x70);
}
// fp32 -> (hi,lo) bf16x2 packers
__device__ __forceinline__ void split2(float x, float y, uint32_t& hi, uint32_t& lo) {
    __nv_bfloat16 hx = __float2bfloat16(x), hy = __float2bfloat16(y);
    float lx = x - __bfloat162float(hx), ly = y - __bfloat162float(hy);
    hi = ((uint32_t)__bfloat16_as_ushort(hy) << 16) | (uint32_t)__bfloat16_as_ushort(hx);
    __nv_bfloat16 gx = __float2bfloat16(lx), gy = __float2bfloat16(ly);
    lo = ((uint32_t)__bfloat16_as_ushort(gy) << 16) | (uint32_t)__bfloat16_as_ushort(gx);
}

#define OFF_AH 1024
#define OFF_AL (1024 + 16384)
#define OFF_BH (1024 + 32768)
#define OFF_BL (1024 + 49152)
#define SMEM_TC_BYTES (1024 + 65536)

#if HAS_TCGEN05
// ---------------- tcgen05-only helpers ----------------
__device__ __forceinline__ uint32_t elect1() {
    uint32_t p;
    asm volatile("{ .reg .pred p; elect.sync _|p, 0xFFFFFFFF; selp.b32 %0,1,0,p; }"
                 : "=r"(p));
    return p;
}
__device__ __forceinline__ void mbar_wait(uint32_t addr, uint32_t parity) {
    uint32_t done;
    asm volatile(
        "{\n\t.reg .pred p;\n\t"
        "mbarrier.try_wait.parity.acquire.cta.shared::cta.b64 p, [%1], %2;\n\t"
        "selp.b32 %0,1,0,p;\n\t}"
        : "=r"(done) : "r"(addr), "r"(parity) : "memory");
    if (!done) {
        asm volatile(
            "{\n\t.reg .pred P1;\n\t"
            "WL%=:\n\t"
            "mbarrier.try_wait.parity.acquire.cta.shared::cta.b64 P1, [%0], %1, 0x989680;\n\t"
            "@P1 bra.uni WD%=;\n\t"
            "bra.uni WL%=;\n\t"
            "WD%=:\n\t}"
            :: "r"(addr), "r"(parity) : "memory");
    }
}
__device__ __forceinline__ void mma_ss(uint32_t d, uint64_t a, uint64_t b,
                                       uint32_t idesc, uint32_t en) {
    asm volatile(
        "{\n\t.reg .pred p;\n\tsetp.ne.u32 p, %4, 0;\n\t"
        "tcgen05.mma.cta_group::1.kind::f16 [%0], %1, %2, %3, {%5,%5,%5,%5}, p;\n\t}"
        :: "r"(d), "l"(a), "l"(b), "r"(idesc), "r"(en), "r"(0u) : "memory");
}
__device__ __forceinline__ void ldtm32(uint32_t* r, uint32_t addr) {
    asm volatile(
        "tcgen05.ld.sync.aligned.32x32b.x32.b32 "
        "{%0,%1,%2,%3,%4,%5,%6,%7,%8,%9,%10,%11,%12,%13,%14,%15,"
        "%16,%17,%18,%19,%20,%21,%22,%23,%24,%25,%26,%27,%28,%29,%30,%31},[%32];"
        : "=r"(r[0]),"=r"(r[1]),"=r"(r[2]),"=r"(r[3]),"=r"(r[4]),"=r"(r[5]),
          "=r"(r[6]),"=r"(r[7]),"=r"(r[8]),"=r"(r[9]),"=r"(r[10]),"=r"(r[11]),
          "=r"(r[12]),"=r"(r[13]),"=r"(r[14]),"=r"(r[15]),"=r"(r[16]),"=r"(r[17]),
          "=r"(r[18]),"=r"(r[19]),"=r"(r[20]),"=r"(r[21]),"=r"(r[22]),"=r"(r[23]),
          "=r"(r[24]),"=r"(r[25]),"=r"(r[26]),"=r"(r[27]),"=r"(r[28]),"=r"(r[29]),
          "=r"(r[30]),"=r"(r[31])
        : "r"(addr));
}
static constexpr uint32_t IDESC_128 =
    (1u << 4) | (1u << 7) | (1u << 10) | ((128u / 8) << 17) | ((128u / 16) << 24);
static constexpr uint64_t DBASE =
    (2ull << 61) | (1ull << 46) | (64ull << 32) | (1ull << 16);
#else
// ---------------- mma.sync fallback helpers ----------------
__device__ __forceinline__ void ldsm4(uint32_t* r, uint32_t addr) {
    asm volatile("ldmatrix.sync.aligned.m8n8.x4.shared.b16 {%0,%1,%2,%3}, [%4];"
                 : "=r"(r[0]), "=r"(r[1]), "=r"(r[2]), "=r"(r[3]) : "r"(addr));
}
__device__ __forceinline__ void mma16816(float* d, const uint32_t* a, const uint32_t* b) {
    asm volatile(
        "mma.sync.aligned.m16n8k16.row.col.f32.bf16.bf16.f32 "
        "{%0,%1,%2,%3},{%4,%5,%6,%7},{%8,%9},{%0,%1,%2,%3};"
        : "+f"(d[0]), "+f"(d[1]), "+f"(d[2]), "+f"(d[3])
        : "r"(a[0]), "r"(a[1]), "r"(a[2]), "r"(a[3]), "r"(b[0]), "r"(b[1]));
}
#endif

// ---------------------------------------------------------------------------
// GEMM: C[m,n] = sum_k A[m,k]*Bw[n,k]  (A = g_A, K-major both operands)
// CTA tile M=128 x N=128, K-slice z (split-K). BK=64 fp32 -> hi/lo bf16
// planes in SW128-swizzled SMEM. Output fp32 partials -> g_part[z][m][n].
// ---------------------------------------------------------------------------
__global__ void __launch_bounds__(256) sgemm_tc(const float* __restrict__ Bw,
                                                int N, int klen) {
    extern __shared__ char smem[];
    uint32_t sb = smem_u32(smem);
    int tid = threadIdx.x, wid = tid >> 5, lid = tid & 31;
    int m0 = blockIdx.y * 128, n0 = blockIdx.x * 128, z = blockIdx.z;
    int nch = klen / 64;
    long k0 = (long)z * klen;
    int f4 = tid & 15, rb = tid >> 4;
    const float4 z4 = make_float4(0.f, 0.f, 0.f, 0.f);

#if HAS_TCGEN05
    // ---------------- tcgen05 path ----------------
    if (wid == 0) {
        asm volatile("tcgen05.alloc.cta_group::1.sync.aligned.shared::cta.b32 [%0], %1;"
                     :: "r"(sb), "r"(128u) : "memory");
        asm volatile("tcgen05.relinquish_alloc_permit.cta_group::1.sync.aligned;");
    }
    if (tid == 0) {
        asm volatile("mbarrier.init.shared.b64 [%0], 1;" :: "r"(sb + 8) : "memory");
    }
    __syncthreads();
    uint32_t tmem;
    asm volatile("ld.shared.b32 %0,[%1];" : "=r"(tmem) : "r"(sb));

    uint32_t lead = 0;
    if (wid == 0) lead = elect1();

    const uint64_t dAH = DBASE | (((uint64_t)(sb + OFF_AH) >> 4) & 0x3FFF);
    const uint64_t dAL = DBASE | (((uint64_t)(sb + OFF_AL) >> 4) & 0x3FFF);
    const uint64_t dBH = DBASE | (((uint64_t)(sb + OFF_BH) >> 4) & 0x3FFF);
    const uint64_t dBL = DBASE | (((uint64_t)(sb + OFF_BL) >> 4) & 0x3FFF);

    for (int ch = 0; ch < nch; ch++) {
        if (ch > 0) mbar_wait(sb + 8, (ch - 1) & 1);
        long kc = k0 + (long)ch * 64 + f4 * 4;
#pragma unroll
        for (int p = 0; p < 8; p++) {
            int r = p * 16 + rb;
            int gm = m0 + r, gn = n0 + r;
            float4 av = (gm < MM) ? *(const float4*)(g_A + (long)gm * KKT + kc) : z4;
            float4 bv = (gn < N)  ? *(const float4*)(Bw + (long)gn * KKT + kc) : z4;
            uint32_t sw = swz((uint32_t)(r * 128 + f4 * 8));
            uint32_t h0, l0, h1, l1;
            split2(av.x, av.y, h0, l0); split2(av.z, av.w, h1, l1);
            *(uint2*)(smem + OFF_AH + sw) = make_uint2(h0, h1);
            *(uint2*)(smem + OFF_AL + sw) = make_uint2(l0, l1);
            split2(bv.x, bv.y, h0, l0); split2(bv.z, bv.w, h1, l1);
            *(uint2*)(smem + OFF_BH + sw) = make_uint2(h0, h1);
            *(uint2*)(smem + OFF_BL + sw) = make_uint2(l0, l1);
        }
        __syncthreads();
        if (lead) {
            asm volatile("fence.proxy.async.shared::cta;" ::: "memory");
            uint32_t accb = (ch > 0) ? 1u : 0u;
#pragma unroll
            for (int ks = 0; ks < 4; ks++)
                mma_ss(tmem, dAH + 2 * ks, dBH + 2 * ks, IDESC_128,
                       (ks > 0) ? 1u : accb);
#pragma unroll
            for (int ks = 0; ks < 4; ks++)
                mma_ss(tmem, dAH + 2 * ks, dBL + 2 * ks, IDESC_128, 1u);
#pragma unroll
            for (int ks = 0; ks < 4; ks++)
                mma_ss(tmem, dAL + 2 * ks, dBH + 2 * ks, IDESC_128, 1u);
            asm volatile(
                "tcgen05.commit.cta_group::1.mbarrier::arrive::one.shared::cluster.b64 [%0];"
                :: "r"(sb + 8) : "memory");
        }
    }
    mbar_wait(sb + 8, (nch - 1) & 1);
    asm volatile("tcgen05.fence::after_thread_sync;" ::: "memory");

    if (tid < 128) {
        int m = m0 + wid * 32 + lid;
#pragma unroll
        for (int cb = 0; cb < 4; cb++) {
            uint32_t r[32];
            ldtm32(r, tmem + cb * 32);
            asm volatile("tcgen05.wait::ld.sync.aligned;" ::: "memory");
            if (m < MM) {
                float* dst = g_part + (long)z * MM * N + (long)m * N;
#pragma unroll
                for (int j = 0; j < 32; j++) {
                    int n = n0 + cb * 32 + j;
                    if (n < N) dst[n] = __uint_as_float(r[j]);
                }
            }
        }
    }
    __syncthreads();
    if (wid == 0) {
        asm volatile("tcgen05.dealloc.cta_group::1.sync.aligned.b32 %0, %1;"
                     :: "r"(tmem), "r"(128u));
    }
#else
    // ---------------- mma.sync bf16 fallback path ----------------
    // 8 warps: warp (wm, wn), wm = wid&3 over M (32 rows), wn = wid>>2 over N (64 cols)
    int wm = wid & 3, wn = wid >> 2;
    float acc[2][8][4];
#pragma unroll
    for (int i = 0; i < 2; i++)
#pragma unroll
        for (int j = 0; j < 8; j++)
#pragma unroll
            for (int q = 0; q < 4; q++) acc[i][j][q] = 0.f;

    for (int ch = 0; ch < nch; ch++) {
        long kc = k0 + (long)ch * 64 + f4 * 4;
#pragma unroll
        for (int p = 0; p < 8; p++) {
            int r = p * 16 + rb;
            int gm = m0 + r, gn = n0 + r;
            float4 av = (gm < MM) ? *(const float4*)(g_A + (long)gm * KKT + kc) : z4;
            float4 bv = (gn < N)  ? *(const float4*)(Bw + (long)gn * KKT + kc) : z4;
            uint32_t sw = swz((uint32_t)(r * 128 + f4 * 8));
            uint32_t h0, l0, h1, l1;
            split2(av.x, av.y, h0, l0); split2(av.z, av.w, h1, l1);
            *(uint2*)(smem + OFF_AH + sw) = make_uint2(h0, h1);
            *(uint2*)(smem + OFF_AL + sw) = make_uint2(l0, l1);
            split2(bv.x, bv.y, h0, l0); split2(bv.z, bv.w, h1, l1);
            *(uint2*)(smem + OFF_BH + sw) = make_uint2(h0, h1);
            *(uint2*)(smem + OFF_BL + sw) = make_uint2(l0, l1);
        }
        __syncthreads();

#pragma unroll
        for (int ks = 0; ks < 4; ks++) {
            // A fragments (16x16) for 2 m-subtiles, hi+lo planes
            uint32_t ah[2][4], al[2][4];
#pragma unroll
            for (int mf = 0; mf < 2; mf++) {
                uint32_t row = (uint32_t)(wm * 32 + mf * 16 + (lid & 15));
                uint32_t col = (uint32_t)(ks * 32 + (lid >> 4) * 16);
                uint32_t o = swz(row * 128 + col);
                ldsm4(ah[mf], sb + OFF_AH + o);
                ldsm4(al[mf], sb + OFF_AL + o);
            }
            // B fragments: 4 x4-loads cover n64 (2 n8-frags per load)
#pragma unroll
            for (int nq = 0; nq < 4; nq++) {
                uint32_t row = (uint32_t)(wn * 64 + nq * 16 + (lid & 7) +
                                          ((lid >> 4) & 1) * 8);
                uint32_t col = (uint32_t)(ks * 32 + ((lid >> 3) & 1) * 16);
                uint32_t o = swz(row * 128 + col);
                uint32_t bh[4], bl[4];
                ldsm4(bh, sb + OFF_BH + o);
                ldsm4(bl, sb + OFF_BL + o);
#pragma unroll
                for (int mf = 0; mf < 2; mf++) {
                    mma16816(acc[mf][2 * nq + 0], ah[mf], bh + 0);
                    mma16816(acc[mf][2 * nq + 0], ah[mf], bl + 0);
                    mma16816(acc[mf][2 * nq + 0], al[mf], bh + 0);
                    mma16816(acc[mf][2 * nq + 1], ah[mf], bh + 2);
                    mma16816(acc[mf][2 * nq + 1], ah[mf], bl + 2);
                    mma16816(acc[mf][2 * nq + 1], al[mf], bh + 2);
                }
            }
        }
        __syncthreads();
    }

    // epilogue: d-frag mapping: rows lane/4 (+8), cols (lane%4)*2 (+1)
    float* dst = g_part + (long)z * MM * N;
    int gr = lid >> 2, gc = (lid & 3) << 1;
#pragma unroll
    for (int mf = 0; mf < 2; mf++) {
#pragma unroll
        for (int nf = 0; nf < 8; nf++) {
            int mrow = m0 + wm * 32 + mf * 16 + gr;
            int ncol = n0 + wn * 64 + nf * 8 + gc;
            if (mrow < MM) {
                if (ncol < N)     dst[(long)mrow * N + ncol]     = acc[mf][nf][0];
                if (ncol + 1 < N) dst[(long)mrow * N + ncol + 1] = acc[mf][nf][1];
            }
            if (mrow + 8 < MM) {
                if (ncol < N)     dst[(long)(mrow + 8) * N + ncol]     = acc[mf][nf][2];
                if (ncol + 1 < N) dst[(long)(mrow + 8) * N + ncol + 1] = acc[mf][nf][3];
            }
        }
    }
#endif
}

// ---------------------------------------------------------------------------
// im2col from x [8,2048,10,10], k=3 s=2 p=1  -> A[m][c*9+u*3+v]
// ---------------------------------------------------------------------------
__global__ void im2col_x_k(const float* __restrict__ x) {
    int t = blockIdx.x * 256 + threadIdx.x;
    if (t >= MM * CCH) return;
    int c = t & 2047, m = t >> 11;
    int b = m / 25, pos = m % 25;
    int oy = pos / 5, ox = pos % 5;
    const float* xb = x + ((long)(b * CCH + c)) * 100;
    float* ab = g_A + (long)m * KKT + c * 9;
#pragma unroll
    for (int u = 0; u < 3; u++) {
        int iy = 2 * oy - 1 + u;
#pragma unroll
        for (int v = 0; v < 3; v++) {
            int ix = 2 * ox - 1 + v;
            float val = (iy >= 0 && iy < 10 && ix >= 0 && ix < 10) ? xb[iy * 10 + ix] : 0.f;
            ab[u * 3 + v] = val;
        }
    }
}

// im2col from a 5x5 map (layout [b][pos][c]), k=3 s=1 p=1. sel: 0->g_f, 1->g_xs
__global__ void im2col5_k(int sel) {
    int t = blockIdx.x * 256 + threadIdx.x;
    if (t >= MM * CCH) return;
    int c = t & 2047, m = t >> 11;
    int b = m / 25, pos = m % 25;
    int oy = pos / 5, ox = pos % 5;
    const float* src = sel ? g_xs : g_f;
    float* ab = g_A + (long)m * KKT + c * 9;
#pragma unroll
    for (int u = 0; u < 3; u++) {
        int iy = oy - 1 + u;
#pragma unroll
        for (int v = 0; v < 3; v++) {
            int ix = ox - 1 + v;
            float val = (iy >= 0 && iy < 5 && ix >= 0 && ix < 5)
                        ? src[(b * 25 + iy * 5 + ix) * CCH + c] : 0.f;
            ab[u * 3 + v] = val;
        }
    }
}

// split-K reduction: dst_sel 0 -> g_C, 1 -> g_h, 2 -> g_L
__global__ void reduce_k(int dst_sel, int N, int nz) {
    int i = blockIdx.x * 256 + threadIdx.x;
    int tot = MM * N;
    if (i >= tot) return;
    float s = 0.f;
    for (int zz = 0; zz < nz; zz++) s += g_part[(long)zz * tot + i];
    float* dst = (dst_sel == 0) ? g_C : ((dst_sel == 1) ? g_h : g_L);
    dst[i] = s;
}

// BN batch statistics over m (200 samples) per channel n (of g_C)
__global__ void bn_stats_k() {
    __shared__ float ss[2], ss2[2];
    int n = blockIdx.x, tid = threadIdx.x;
    float s = 0.f, s2 = 0.f;
    for (int m = tid; m < MM; m += 64) {
        float v = g_C[(long)m * CCH + n];
        s += v; s2 += v * v;
    }
#pragma unroll
    for (int o = 16; o > 0; o >>= 1) {
        s  += __shfl_xor_sync(0xffffffffu, s,  o);
        s2 += __shfl_xor_sync(0xffffffffu, s2, o);
    }
    if ((tid & 31) == 0) { ss[tid >> 5] = s; ss2[tid >> 5] = s2; }
    __syncthreads();
    if (tid == 0) {
        float S = ss[0] + ss[1], S2 = ss2[0] + ss2[1];
        float mean = S * (1.f / 200.f);
        float var  = S2 * (1.f / 200.f) - mean * mean;
        g_mean[n] = mean;
        g_rstd[n] = rsqrtf(var + 1e-5f);
    }
}

// dst_sel: 0 -> g_f, 1 -> g_xs
__global__ void bn_apply_k(const float* __restrict__ gam, const float* __restrict__ bet,
                           int dst_sel, int relu) {
    int i = blockIdx.x * 256 + threadIdx.x;
    if (i >= MM * CCH) return;
    int n = i & 2047;
    float v = (g_C[i] - g_mean[n]) * g_rstd[n] * gam[n] + bet[n];
    if (relu) v = fmaxf(v, 0.f);
    float* dst = dst_sel ? g_xs : g_f;
    dst[i] = v;
}

// fc2 (4x512) per (b,pos) on relu(g_h); theta -> output; 9 grid pts -> g_grids
__global__ void fc2_theta_k(const float* __restrict__ fc2_w, float* __restrict__ out_theta) {
    int m = blockIdx.x;
    int tid = threadIdx.x;    // 128
    __shared__ float sh[512];
    __shared__ float sp[4];
    for (int i = tid; i < 512; i += 128) sh[i] = fmaxf(g_h[m * 512 + i], 0.f);
    __syncthreads();
    int w = tid >> 5, lane = tid & 31;
    float s = 0.f;
    for (int j = lane; j < 512; j += 32) s += sh[j] * fc2_w[w * 512 + j];
#pragma unroll
    for (int o = 16; o > 0; o >>= 1) s += __shfl_xor_sync(0xffffffffu, s, o);
    if (lane == 0) sp[w] = s;
    __syncthreads();
    if (tid == 0) {
        float p0 = sp[0], p1 = sp[1], p2 = sp[2], p3 = sp[3];
        float th[6] = {1.f + p0, 0.f, p1, 0.f, 1.f + p2, p3};
#pragma unroll
        for (int t = 0; t < 6; t++) out_theta[m * 6 + t] = th[t];
        int pi = (m % 25) / 5, pj = (m % 25) % 5;
#pragma unroll
        for (int u = 0; u < 3; u++)
#pragma unroll
            for (int v = 0; v < 3; v++) {
                float lx = (float)(pj + v) * (1.f / 3.f) - 1.f;
                float ly = (float)(pi + u) * (1.f / 3.f) - 1.f;
                int pt = m * 9 + u * 3 + v;
                g_grids[pt * 2 + 0] = (1.f + p0) * lx + p1;
                g_grids[pt * 2 + 1] = (1.f + p2) * ly + p3;
            }
    }
}

// bilinear sample of f (zero-padded ring), writes im2col A[m][c*9+k]
__global__ void sample_k(void) {
    int pt = blockIdx.x;          // m*9 + k
    int m = pt / 9, k = pt % 9;
    int b = m / 25;
    float gx = (g_grids[pt * 2 + 0] + 1.f) * 3.f;
    float gy = (g_grids[pt * 2 + 1] + 1.f) * 3.f;
    float x0f = floorf(gx), y0f = floorf(gy);
    int   x0i = (int)x0f,  y0i = (int)y0f;
    float wx1 = gx - x0f, wx0 = 1.f - wx1;
    float wy1 = gy - y0f, wy0 = 1.f - wy1;
    int   cx[2] = {x0i, x0i + 1}, cy[2] = {y0i, y0i + 1};
    float wxx[2] = {wx0, wx1},    wyy[2] = {wy0, wy1};
    float wgt[4];
    int   off[4];
#pragma unroll
    for (int a = 0; a < 2; a++)
#pragma unroll
        for (int c2 = 0; c2 < 2; c2++) {
            int xi = cx[c2], yi = cy[a];
            bool val = (xi >= 1 && xi <= 5 && yi >= 1 && yi <= 5);
            wgt[a * 2 + c2] = val ? wyy[a] * wxx[c2] : 0.f;
            off[a * 2 + c2] = val ? ((b * 25 + (yi - 1) * 5 + (xi - 1)) * CCH) : 0;
        }
    float* ab = g_A + (long)m * KKT + k;
    for (int c = threadIdx.x; c < CCH; c += blockDim.x) {
        float v = wgt[0] * g_f[off[0] + c] + wgt[1] * g_f[off[1] + c]
                + wgt[2] * g_f[off[2] + c] + wgt[3] * g_f[off[3] + c];
        ab[(long)c * 9] = v;
    }
}

// joint softmax over 201*25 per batch
__global__ void softmax_k(const float* __restrict__ bias, float* __restrict__ out) {
    int b = blockIdx.x;
    int tid = threadIdx.x;            // 512
    __shared__ float sm[5025];
    __shared__ float red[512];
    float lmax = -3.0e38f;
    for (int idx = tid; idx < 5025; idx += 512) {
        int o = idx / 25, pos = idx % 25;
        float v = g_L[(b * 25 + pos) * 201 + o] + bias[o];
        sm[idx] = v;
        lmax = fmaxf(lmax, v);
    }
    red[tid] = lmax;
    __syncthreads();
    for (int s = 256; s > 0; s >>= 1) {
        if (tid < s) red[tid] = fmaxf(red[tid], red[tid + s]);
        __syncthreads();
    }
    float mx = red[0];
    __syncthreads();
    float lsum = 0.f;
    for (int idx = tid; idx < 5025; idx += 512) {
        float e = expf(sm[idx] - mx);
        sm[idx] = e;
        lsum += e;
    }
    red[tid] = lsum;
    __syncthreads();
    for (int s = 256; s > 0; s >>= 1) {
        if (tid < s) red[tid] += red[tid + s];
        __syncthreads();
    }
    float inv = 1.f / red[0];
    __syncthreads();
    float* s_out = out + 1608;
    for (int idx = tid; idx < 5025; idx += 512)
        s_out[b * 5025 + idx] = sm[idx] * inv;
    for (int o = tid; o < 201; o += 512) {
        float acc = 0.f;
        for (int pos = 0; pos < 25; pos++) acc += sm[o * 25 + pos];
        out[b * 201 + o] = acc * inv;
    }
}

// ---------------------------------------------------------------------------
extern "C" void kernel_launch(void* const* d_in, const int* in_sizes, int n_in,
                              void* d_out, int out_size) {
    const float* x           = (const float*)d_in[0];
    const float* conv_last_w = (const float*)d_in[3];
    const float* bn_last_g   = (const float*)d_in[4];
    const float* bn_last_b   = (const float*)d_in[5];
    const float* loc_w1      = (const float*)d_in[6];
    const float* loc_g1      = (const float*)d_in[7];
    const float* loc_b1      = (const float*)d_in[8];
    const float* loc_w2      = (const float*)d_in[9];
    const float* loc_g2      = (const float*)d_in[10];
    const float* loc_b2      = (const float*)d_in[11];
    const float* fc1_w       = (const float*)d_in[12];
    const float* fc2_w       = (const float*)d_in[13];
    const float* conv_stn_w  = (const float*)d_in[14];
    const float* conv_stn_b  = (const float*)d_in[15];
    float* out = (float*)d_out;
    float* out_theta = out + 1608 + 40200;

    cudaFuncSetAttribute(sgemm_tc, cudaFuncAttributeMaxDynamicSharedMemorySize,
                         SMEM_TC_BYTES);

    const int ELT_BLOCKS = (MM * CCH + 255) / 256;   // 1600

    // ---- backbone tail: conv_last + BN -> f ----
    im2col_x_k<<<ELT_BLOCKS, 256>>>(x);
    sgemm_tc<<<dim3(16, 2, 8), 256, SMEM_TC_BYTES>>>(conv_last_w, 2048, 2304);
    reduce_k<<<(MM * 2048 + 255) / 256, 256>>>(0, 2048, 8);
    bn_stats_k<<<2048, 64>>>();
    bn_apply_k<<<ELT_BLOCKS, 256>>>(bn_last_g, bn_last_b, 0, 0);

    // ---- localization conv1 ----
    im2col5_k<<<ELT_BLOCKS, 256>>>(0);
    sgemm_tc<<<dim3(16, 2, 8), 256, SMEM_TC_BYTES>>>(loc_w1, 2048, 2304);
    reduce_k<<<(MM * 2048 + 255) / 256, 256>>>(0, 2048, 8);
    bn_stats_k<<<2048, 64>>>();
    bn_apply_k<<<ELT_BLOCKS, 256>>>(loc_g1, loc_b1, 1, 1);

    // ---- localization conv2 ----
    im2col5_k<<<ELT_BLOCKS, 256>>>(1);
    sgemm_tc<<<dim3(16, 2, 8), 256, SMEM_TC_BYTES>>>(loc_w2, 2048, 2304);
    reduce_k<<<(MM * 2048 + 255) / 256, 256>>>(0, 2048, 8);
    bn_stats_k<<<2048, 64>>>();
    bn_apply_k<<<ELT_BLOCKS, 256>>>(loc_g2, loc_b2, 1, 1);

    // ---- fc1 (3x3 conv, 512 outputs) ----
    im2col5_k<<<ELT_BLOCKS, 256>>>(1);
    sgemm_tc<<<dim3(4, 2, 16), 256, SMEM_TC_BYTES>>>(fc1_w, 512, 1152);
    reduce_k<<<(MM * 512 + 255) / 256, 256>>>(1, 512, 16);

    // ---- fc2 + theta + grids ----
    fc2_theta_k<<<200, 128>>>(fc2_w, out_theta);

    // ---- bilinear sample -> im2col A ----
    sample_k<<<1800, 256>>>();

    // ---- conv_stn GEMM ----
    sgemm_tc<<<dim3(2, 2, 32), 256, SMEM_TC_BYTES>>>(conv_stn_w, 201, 576);
    reduce_k<<<(MM * 201 + 255) / 256, 256>>>(2, 201, 32);

    // ---- joint softmax + outputs ----
    softmax_k<<<8, 512>>>(conv_stn_b, out);
}

// round 8
// speedup vs baseline: 6.8186x; 1.5518x over previous
#include <cuda_runtime.h>
#include <cuda_bf16.h>
#include <cstdint>

// ---------------------------------------------------------------------------
// Net_15762529976343 — STN head. 5 GEMMs (M=200, K=18432) on tensor cores.
// Dual path: tcgen05 (only when compiling for sm_103a) else mma.sync bf16.
// Both use bf16 hi/lo 3-term fp32 emulation with fp32 accumulation.
// R8: software-pipelined fallback (register prefetch over MMA) + split-K
//     tuned so every GEMM grid is ~an integer number of 148-SM waves.
// ---------------------------------------------------------------------------

#if defined(__CUDA_ARCH__) && defined(__CUDA_ARCH_FEAT_SM103_ALL)
#define HAS_TCGEN05 1
#else
#define HAS_TCGEN05 0
#endif

#define MM   200
#define KKT  18432
#define CCH  2048

// ---- scratch ----
__device__ __align__(128) float g_A[MM * KKT];
__device__ __align__(128) float g_C[MM * CCH];
__device__ __align__(128) float g_f[MM * CCH];
__device__ __align__(128) float g_xs[MM * CCH];
__device__ __align__(128) float g_h[MM * 512];
__device__ __align__(128) float g_L[MM * 201];
__device__ __align__(128) float g_part[3686400];      // 9*200*2048 fp32 max
__device__ float g_mean[CCH], g_rstd[CCH];
__device__ float g_grids[8 * 225 * 2];

// ---------------------------------------------------------------------------
// helpers
// ---------------------------------------------------------------------------
__device__ __forceinline__ uint32_t smem_u32(const void* p) {
    uint32_t a;
    asm("{ .reg .u64 t; cvta.to.shared.u64 t, %1; cvt.u32.u64 %0, t; }"
        : "=r"(a) : "l"(p));
    return a;
}
__device__ __forceinline__ uint32_t swz(uint32_t off) {
    return off ^ ((off >> 3) & 0x70);
}
// fp32 -> (hi,lo) bf16x2 packers
__device__ __forceinline__ void split2(float x, float y, uint32_t& hi, uint32_t& lo) {
    __nv_bfloat16 hx = __float2bfloat16(x), hy = __float2bfloat16(y);
    float lx = x - __bfloat162float(hx), ly = y - __bfloat162float(hy);
    hi = ((uint32_t)__bfloat16_as_ushort(hy) << 16) | (uint32_t)__bfloat16_as_ushort(hx);
    __nv_bfloat16 gx = __float2bfloat16(lx), gy = __float2bfloat16(ly);
    lo = ((uint32_t)__bfloat16_as_ushort(gy) << 16) | (uint32_t)__bfloat16_as_ushort(gx);
}

#define OFF_AH 1024
#define OFF_AL (1024 + 16384)
#define OFF_BH (1024 + 32768)
#define OFF_BL (1024 + 49152)
#define SMEM_TC_BYTES (1024 + 65536)

#if HAS_TCGEN05
// ---------------- tcgen05-only helpers ----------------
__device__ __forceinline__ uint32_t elect1() {
    uint32_t p;
    asm volatile("{ .reg .pred p; elect.sync _|p, 0xFFFFFFFF; selp.b32 %0,1,0,p; }"
                 : "=r"(p));
    return p;
}
__device__ __forceinline__ void mbar_wait(uint32_t addr, uint32_t parity) {
    uint32_t done;
    asm volatile(
        "{\n\t.reg .pred p;\n\t"
        "mbarrier.try_wait.parity.acquire.cta.shared::cta.b64 p, [%1], %2;\n\t"
        "selp.b32 %0,1,0,p;\n\t}"
        : "=r"(done) : "r"(addr), "r"(parity) : "memory");
    if (!done) {
        asm volatile(
            "{\n\t.reg .pred P1;\n\t"
            "WL%=:\n\t"
            "mbarrier.try_wait.parity.acquire.cta.shared::cta.b64 P1, [%0], %1, 0x989680;\n\t"
            "@P1 bra.uni WD%=;\n\t"
            "bra.uni WL%=;\n\t"
            "WD%=:\n\t}"
            :: "r"(addr), "r"(parity) : "memory");
    }
}
__device__ __forceinline__ void mma_ss(uint32_t d, uint64_t a, uint64_t b,
                                       uint32_t idesc, uint32_t en) {
    asm volatile(
        "{\n\t.reg .pred p;\n\tsetp.ne.u32 p, %4, 0;\n\t"
        "tcgen05.mma.cta_group::1.kind::f16 [%0], %1, %2, %3, {%5,%5,%5,%5}, p;\n\t}"
        :: "r"(d), "l"(a), "l"(b), "r"(idesc), "r"(en), "r"(0u) : "memory");
}
__device__ __forceinline__ void ldtm32(uint32_t* r, uint32_t addr) {
    asm volatile(
        "tcgen05.ld.sync.aligned.32x32b.x32.b32 "
        "{%0,%1,%2,%3,%4,%5,%6,%7,%8,%9,%10,%11,%12,%13,%14,%15,"
        "%16,%17,%18,%19,%20,%21,%22,%23,%24,%25,%26,%27,%28,%29,%30,%31},[%32];"
        : "=r"(r[0]),"=r"(r[1]),"=r"(r[2]),"=r"(r[3]),"=r"(r[4]),"=r"(r[5]),
          "=r"(r[6]),"=r"(r[7]),"=r"(r[8]),"=r"(r[9]),"=r"(r[10]),"=r"(r[11]),
          "=r"(r[12]),"=r"(r[13]),"=r"(r[14]),"=r"(r[15]),"=r"(r[16]),"=r"(r[17]),
          "=r"(r[18]),"=r"(r[19]),"=r"(r[20]),"=r"(r[21]),"=r"(r[22]),"=r"(r[23]),
          "=r"(r[24]),"=r"(r[25]),"=r"(r[26]),"=r"(r[27]),"=r"(r[28]),"=r"(r[29]),
          "=r"(r[30]),"=r"(r[31])
        : "r"(addr));
}
static constexpr uint32_t IDESC_128 =
    (1u << 4) | (1u << 7) | (1u << 10) | ((128u / 8) << 17) | ((128u / 16) << 24);
static constexpr uint64_t DBASE =
    (2ull << 61) | (1ull << 46) | (64ull << 32) | (1ull << 16);
#else
// ---------------- mma.sync fallback helpers ----------------
__device__ __forceinline__ void ldsm4(uint32_t* r, uint32_t addr) {
    asm volatile("ldmatrix.sync.aligned.m8n8.x4.shared.b16 {%0,%1,%2,%3}, [%4];"
                 : "=r"(r[0]), "=r"(r[1]), "=r"(r[2]), "=r"(r[3]) : "r"(addr));
}
__device__ __forceinline__ void mma16816(float* d, const uint32_t* a, const uint32_t* b) {
    asm volatile(
        "mma.sync.aligned.m16n8k16.row.col.f32.bf16.bf16.f32 "
        "{%0,%1,%2,%3},{%4,%5,%6,%7},{%8,%9},{%0,%1,%2,%3};"
        : "+f"(d[0]), "+f"(d[1]), "+f"(d[2]), "+f"(d[3])
        : "r"(a[0]), "r"(a[1]), "r"(a[2]), "r"(a[3]), "r"(b[0]), "r"(b[1]));
}
#endif

// ---------------------------------------------------------------------------
// GEMM: C[m,n] = sum_k A[m,k]*Bw[n,k]  (A = g_A, K-major both operands)
// CTA tile M=128 x N=128, K-slice z (split-K). BK=64 fp32 -> hi/lo bf16
// planes in SW128-swizzled SMEM. Output fp32 partials -> g_part[z][m][n].
// ---------------------------------------------------------------------------
__global__ void __launch_bounds__(256, 1) sgemm_tc(const float* __restrict__ Bw,
                                                   int N, int klen) {
    extern __shared__ char smem[];
    uint32_t sb = smem_u32(smem);
    int tid = threadIdx.x, wid = tid >> 5, lid = tid & 31;
    int m0 = blockIdx.y * 128, n0 = blockIdx.x * 128, z = blockIdx.z;
    int nch = klen / 64;
    long k0 = (long)z * klen;
    int f4 = tid & 15, rb = tid >> 4;
    const float4 z4 = make_float4(0.f, 0.f, 0.f, 0.f);

#if HAS_TCGEN05
    // ---------------- tcgen05 path ----------------
    if (wid == 0) {
        asm volatile("tcgen05.alloc.cta_group::1.sync.aligned.shared::cta.b32 [%0], %1;"
                     :: "r"(sb), "r"(128u) : "memory");
        asm volatile("tcgen05.relinquish_alloc_permit.cta_group::1.sync.aligned;");
    }
    if (tid == 0) {
        asm volatile("mbarrier.init.shared.b64 [%0], 1;" :: "r"(sb + 8) : "memory");
    }
    __syncthreads();
    uint32_t tmem;
    asm volatile("ld.shared.b32 %0,[%1];" : "=r"(tmem) : "r"(sb));

    uint32_t lead = 0;
    if (wid == 0) lead = elect1();

    const uint64_t dAH = DBASE | (((uint64_t)(sb + OFF_AH) >> 4) & 0x3FFF);
    const uint64_t dAL = DBASE | (((uint64_t)(sb + OFF_AL) >> 4) & 0x3FFF);
    const uint64_t dBH = DBASE | (((uint64_t)(sb + OFF_BH) >> 4) & 0x3FFF);
    const uint64_t dBL = DBASE | (((uint64_t)(sb + OFF_BL) >> 4) & 0x3FFF);

    for (int ch = 0; ch < nch; ch++) {
        if (ch > 0) mbar_wait(sb + 8, (ch - 1) & 1);
        long kc = k0 + (long)ch * 64 + f4 * 4;
#pragma unroll
        for (int p = 0; p < 8; p++) {
            int r = p * 16 + rb;
            int gm = m0 + r, gn = n0 + r;
            float4 av = (gm < MM) ? *(const float4*)(g_A + (long)gm * KKT + kc) : z4;
            float4 bv = (gn < N)  ? *(const float4*)(Bw + (long)gn * KKT + kc) : z4;
            uint32_t sw = swz((uint32_t)(r * 128 + f4 * 8));
            uint32_t h0, l0, h1, l1;
            split2(av.x, av.y, h0, l0); split2(av.z, av.w, h1, l1);
            *(uint2*)(smem + OFF_AH + sw) = make_uint2(h0, h1);
            *(uint2*)(smem + OFF_AL + sw) = make_uint2(l0, l1);
            split2(bv.x, bv.y, h0, l0); split2(bv.z, bv.w, h1, l1);
            *(uint2*)(smem + OFF_BH + sw) = make_uint2(h0, h1);
            *(uint2*)(smem + OFF_BL + sw) = make_uint2(l0, l1);
        }
        __syncthreads();
        if (lead) {
            asm volatile("fence.proxy.async.shared::cta;" ::: "memory");
            uint32_t accb = (ch > 0) ? 1u : 0u;
#pragma unroll
            for (int ks = 0; ks < 4; ks++)
                mma_ss(tmem, dAH + 2 * ks, dBH + 2 * ks, IDESC_128,
                       (ks > 0) ? 1u : accb);
#pragma unroll
            for (int ks = 0; ks < 4; ks++)
                mma_ss(tmem, dAH + 2 * ks, dBL + 2 * ks, IDESC_128, 1u);
#pragma unroll
            for (int ks = 0; ks < 4; ks++)
                mma_ss(tmem, dAL + 2 * ks, dBH + 2 * ks, IDESC_128, 1u);
            asm volatile(
                "tcgen05.commit.cta_group::1.mbarrier::arrive::one.shared::cluster.b64 [%0];"
                :: "r"(sb + 8) : "memory");
        }
    }
    mbar_wait(sb + 8, (nch - 1) & 1);
    asm volatile("tcgen05.fence::after_thread_sync;" ::: "memory");

    if (tid < 128) {
        int m = m0 + wid * 32 + lid;
#pragma unroll
        for (int cb = 0; cb < 4; cb++) {
            uint32_t r[32];
            ldtm32(r, tmem + cb * 32);
            asm volatile("tcgen05.wait::ld.sync.aligned;" ::: "memory");
            if (m < MM) {
                float* dst = g_part + (long)z * MM * N + (long)m * N;
#pragma unroll
                for (int j = 0; j < 32; j++) {
                    int n = n0 + cb * 32 + j;
                    if (n < N) dst[n] = __uint_as_float(r[j]);
                }
            }
        }
    }
    __syncthreads();
    if (wid == 0) {
        asm volatile("tcgen05.dealloc.cta_group::1.sync.aligned.b32 %0, %1;"
                     :: "r"(tmem), "r"(128u));
    }
#else
    // ---------------- mma.sync bf16 fallback path (pipelined) ----------------
    // 8 warps: warp (wm, wn), wm = wid&3 over M (32 rows), wn = wid>>2 over N (64 cols)
    int wm = wid & 3, wn = wid >> 2;
    float acc[2][8][4];
#pragma unroll
    for (int i = 0; i < 2; i++)
#pragma unroll
        for (int j = 0; j < 8; j++)
#pragma unroll
            for (int q = 0; q < 4; q++) acc[i][j][q] = 0.f;

    const float* Arow = g_A + (long)(m0 + rb) * KKT + f4 * 4;
    const float* Brow = Bw  + (long)(n0 + rb) * KKT + f4 * 4;
    bool amask[8], bmask[8];
#pragma unroll
    for (int p = 0; p < 8; p++) {
        amask[p] = (m0 + p * 16 + rb) < MM;
        bmask[p] = (n0 + p * 16 + rb) < N;
    }

    float4 a4[8], b4[8];
    // prologue: prefetch chunk 0
#pragma unroll
    for (int p = 0; p < 8; p++) {
        long kc = k0 + (long)p * 16 * KKT;   // unused; placeholder opt-out
    }
#pragma unroll
    for (int p = 0; p < 8; p++) {
        a4[p] = amask[p] ? *(const float4*)(Arow + (long)p * 16 * KKT + k0) : z4;
        b4[p] = bmask[p] ? *(const float4*)(Brow + (long)p * 16 * KKT + k0) : z4;
    }

    for (int ch = 0; ch < nch; ch++) {
        // convert + store current chunk's registers into swizzled bf16 planes
#pragma unroll
        for (int p = 0; p < 8; p++) {
            int r = p * 16 + rb;
            uint32_t sw = swz((uint32_t)(r * 128 + f4 * 8));
            uint32_t h0, l0, h1, l1;
            split2(a4[p].x, a4[p].y, h0, l0); split2(a4[p].z, a4[p].w, h1, l1);
            *(uint2*)(smem + OFF_AH + sw) = make_uint2(h0, h1);
            *(uint2*)(smem + OFF_AL + sw) = make_uint2(l0, l1);
            split2(b4[p].x, b4[p].y, h0, l0); split2(b4[p].z, b4[p].w, h1, l1);
            *(uint2*)(smem + OFF_BH + sw) = make_uint2(h0, h1);
            *(uint2*)(smem + OFF_BL + sw) = make_uint2(l0, l1);
        }
        __syncthreads();

        // issue next chunk's global loads NOW; they complete under the MMAs
        if (ch + 1 < nch) {
            long kc = k0 + (long)(ch + 1) * 64;
#pragma unroll
            for (int p = 0; p < 8; p++) {
                a4[p] = amask[p] ? *(const float4*)(Arow + (long)p * 16 * KKT + kc) : z4;
                b4[p] = bmask[p] ? *(const float4*)(Brow + (long)p * 16 * KKT + kc) : z4;
            }
        }

#pragma unroll
        for (int ks = 0; ks < 4; ks++) {
            // A fragments (16x16) for 2 m-subtiles, hi+lo planes
            uint32_t ah[2][4], al[2][4];
#pragma unroll
            for (int mf = 0; mf < 2; mf++) {
                uint32_t row = (uint32_t)(wm * 32 + mf * 16 + (lid & 15));
                uint32_t col = (uint32_t)(ks * 32 + (lid >> 4) * 16);
                uint32_t o = swz(row * 128 + col);
                ldsm4(ah[mf], sb + OFF_AH + o);
                ldsm4(al[mf], sb + OFF_AL + o);
            }
            // B fragments: 4 x4-loads cover n64 (2 n8-frags per load)
#pragma unroll
            for (int nq = 0; nq < 4; nq++) {
                uint32_t row = (uint32_t)(wn * 64 + nq * 16 + (lid & 7) +
                                          ((lid >> 4) & 1) * 8);
                uint32_t col = (uint32_t)(ks * 32 + ((lid >> 3) & 1) * 16);
                uint32_t o = swz(row * 128 + col);
                uint32_t bh[4], bl[4];
                ldsm4(bh, sb + OFF_BH + o);
                ldsm4(bl, sb + OFF_BL + o);
#pragma unroll
                for (int mf = 0; mf < 2; mf++) {
                    mma16816(acc[mf][2 * nq + 0], ah[mf], bh + 0);
                    mma16816(acc[mf][2 * nq + 0], ah[mf], bl + 0);
                    mma16816(acc[mf][2 * nq + 0], al[mf], bh + 0);
                    mma16816(acc[mf][2 * nq + 1], ah[mf], bh + 2);
                    mma16816(acc[mf][2 * nq + 1], ah[mf], bl + 2);
                    mma16816(acc[mf][2 * nq + 1], al[mf], bh + 2);
                }
            }
        }
        __syncthreads();
    }

    // epilogue: d-frag mapping: rows lane/4 (+8), cols (lane%4)*2 (+1)
    float* dst = g_part + (long)z * MM * N;
    int gr = lid >> 2, gc = (lid & 3) << 1;
#pragma unroll
    for (int mf = 0; mf < 2; mf++) {
#pragma unroll
        for (int nf = 0; nf < 8; nf++) {
            int mrow = m0 + wm * 32 + mf * 16 + gr;
            int ncol = n0 + wn * 64 + nf * 8 + gc;
            if (mrow < MM) {
                if (ncol < N)     dst[(long)mrow * N + ncol]     = acc[mf][nf][0];
                if (ncol + 1 < N) dst[(long)mrow * N + ncol + 1] = acc[mf][nf][1];
            }
            if (mrow + 8 < MM) {
                if (ncol < N)     dst[(long)(mrow + 8) * N + ncol]     = acc[mf][nf][2];
                if (ncol + 1 < N) dst[(long)(mrow + 8) * N + ncol + 1] = acc[mf][nf][3];
            }
        }
    }
#endif
}

// ---------------------------------------------------------------------------
// im2col from x [8,2048,10,10], k=3 s=2 p=1  -> A[m][c*9+u*3+v]
// ---------------------------------------------------------------------------
__global__ void im2col_x_k(const float* __restrict__ x) {
    int t = blockIdx.x * 256 + threadIdx.x;
    if (t >= MM * CCH) return;
    int c = t & 2047, m = t >> 11;
    int b = m / 25, pos = m % 25;
    int oy = pos / 5, ox = pos % 5;
    const float* xb = x + ((long)(b * CCH + c)) * 100;
    float* ab = g_A + (long)m * KKT + c * 9;
#pragma unroll
    for (int u = 0; u < 3; u++) {
        int iy = 2 * oy - 1 + u;
#pragma unroll
        for (int v = 0; v < 3; v++) {
            int ix = 2 * ox - 1 + v;
            float val = (iy >= 0 && iy < 10 && ix >= 0 && ix < 10) ? xb[iy * 10 + ix] : 0.f;
            ab[u * 3 + v] = val;
        }
    }
}

// im2col from a 5x5 map (layout [b][pos][c]), k=3 s=1 p=1. sel: 0->g_f, 1->g_xs
__global__ void im2col5_k(int sel) {
    int t = blockIdx.x * 256 + threadIdx.x;
    if (t >= MM * CCH) return;
    int c = t & 2047, m = t >> 11;
    int b = m / 25, pos = m % 25;
    int oy = pos / 5, ox = pos % 5;
    const float* src = sel ? g_xs : g_f;
    float* ab = g_A + (long)m * KKT + c * 9;
#pragma unroll
    for (int u = 0; u < 3; u++) {
        int iy = oy - 1 + u;
#pragma unroll
        for (int v = 0; v < 3; v++) {
            int ix = ox - 1 + v;
            float val = (iy >= 0 && iy < 5 && ix >= 0 && ix < 5)
                        ? src[(b * 25 + iy * 5 + ix) * CCH + c] : 0.f;
            ab[u * 3 + v] = val;
        }
    }
}

// split-K reduction: dst_sel 0 -> g_C, 1 -> g_h, 2 -> g_L
__global__ void reduce_k(int dst_sel, int N, int nz) {
    int i = blockIdx.x * 256 + threadIdx.x;
    int tot = MM * N;
    if (i >= tot) return;
    float s = 0.f;
    for (int zz = 0; zz < nz; zz++) s += g_part[(long)zz * tot + i];
    float* dst = (dst_sel == 0) ? g_C : ((dst_sel == 1) ? g_h : g_L);
    dst[i] = s;
}

// BN batch statistics over m (200 samples) per channel n (of g_C)
__global__ void bn_stats_k() {
    __shared__ float ss[2], ss2[2];
    int n = blockIdx.x, tid = threadIdx.x;
    float s = 0.f, s2 = 0.f;
    for (int m = tid; m < MM; m += 64) {
        float v = g_C[(long)m * CCH + n];
        s += v; s2 += v * v;
    }
#pragma unroll
    for (int o = 16; o > 0; o >>= 1) {
        s  += __shfl_xor_sync(0xffffffffu, s,  o);
        s2 += __shfl_xor_sync(0xffffffffu, s2, o);
    }
    if ((tid & 31) == 0) { ss[tid >> 5] = s; ss2[tid >> 5] = s2; }
    __syncthreads();
    if (tid == 0) {
        float S = ss[0] + ss[1], S2 = ss2[0] + ss2[1];
        float mean = S * (1.f / 200.f);
        float var  = S2 * (1.f / 200.f) - mean * mean;
        g_mean[n] = mean;
        g_rstd[n] = rsqrtf(var + 1e-5f);
    }
}

// dst_sel: 0 -> g_f, 1 -> g_xs
__global__ void bn_apply_k(const float* __restrict__ gam, const float* __restrict__ bet,
                           int dst_sel, int relu) {
    int i = blockIdx.x * 256 + threadIdx.x;
    if (i >= MM * CCH) return;
    int n = i & 2047;
    float v = (g_C[i] - g_mean[n]) * g_rstd[n] * gam[n] + bet[n];
    if (relu) v = fmaxf(v, 0.f);
    float* dst = dst_sel ? g_xs : g_f;
    dst[i] = v;
}

// fc2 (4x512) per (b,pos) on relu(g_h); theta -> output; 9 grid pts -> g_grids
__global__ void fc2_theta_k(const float* __restrict__ fc2_w, float* __restrict__ out_theta) {
    int m = blockIdx.x;
    int tid = threadIdx.x;    // 128
    __shared__ float sh[512];
    __shared__ float sp[4];
    for (int i = tid; i < 512; i += 128) sh[i] = fmaxf(g_h[m * 512 + i], 0.f);
    __syncthreads();
    int w = tid >> 5, lane = tid & 31;
    float s = 0.f;
    for (int j = lane; j < 512; j += 32) s += sh[j] * fc2_w[w * 512 + j];
#pragma unroll
    for (int o = 16; o > 0; o >>= 1) s += __shfl_xor_sync(0xffffffffu, s, o);
    if (lane == 0) sp[w] = s;
    __syncthreads();
    if (tid == 0) {
        float p0 = sp[0], p1 = sp[1], p2 = sp[2], p3 = sp[3];
        float th[6] = {1.f + p0, 0.f, p1, 0.f, 1.f + p2, p3};
#pragma unroll
        for (int t = 0; t < 6; t++) out_theta[m * 6 + t] = th[t];
        int pi = (m % 25) / 5, pj = (m % 25) % 5;
#pragma unroll
        for (int u = 0; u < 3; u++)
#pragma unroll
            for (int v = 0; v < 3; v++) {
                float lx = (float)(pj + v) * (1.f / 3.f) - 1.f;
                float ly = (float)(pi + u) * (1.f / 3.f) - 1.f;
                int pt = m * 9 + u * 3 + v;
                g_grids[pt * 2 + 0] = (1.f + p0) * lx + p1;
                g_grids[pt * 2 + 1] = (1.f + p2) * ly + p3;
            }
    }
}

// bilinear sample of f (zero-padded ring), writes im2col A[m][c*9+k]
__global__ void sample_k(void) {
    int pt = blockIdx.x;          // m*9 + k
    int m = pt / 9, k = pt % 9;
    int b = m / 25;
    float gx = (g_grids[pt * 2 + 0] + 1.f) * 3.f;
    float gy = (g_grids[pt * 2 + 1] + 1.f) * 3.f;
    float x0f = floorf(gx), y0f = floorf(gy);
    int   x0i = (int)x0f,  y0i = (int)y0f;
    float wx1 = gx - x0f, wx0 = 1.f - wx1;
    float wy1 = gy - y0f, wy0 = 1.f - wy1;
    int   cx[2] = {x0i, x0i + 1}, cy[2] = {y0i, y0i + 1};
    float wxx[2] = {wx0, wx1},    wyy[2] = {wy0, wy1};
    float wgt[4];
    int   off[4];
#pragma unroll
    for (int a = 0; a < 2; a++)
#pragma unroll
        for (int c2 = 0; c2 < 2; c2++) {
            int xi = cx[c2], yi = cy[a];
            bool val = (xi >= 1 && xi <= 5 && yi >= 1 && yi <= 5);
            wgt[a * 2 + c2] = val ? wyy[a] * wxx[c2] : 0.f;
            off[a * 2 + c2] = val ? ((b * 25 + (yi - 1) * 5 + (xi - 1)) * CCH) : 0;
        }
    float* ab = g_A + (long)m * KKT + k;
    for (int c = threadIdx.x; c < CCH; c += blockDim.x) {
        float v = wgt[0] * g_f[off[0] + c] + wgt[1] * g_f[off[1] + c]
                + wgt[2] * g_f[off[2] + c] + wgt[3] * g_f[off[3] + c];
        ab[(long)c * 9] = v;
    }
}

// joint softmax over 201*25 per batch
__global__ void softmax_k(const float* __restrict__ bias, float* __restrict__ out) {
    int b = blockIdx.x;
    int tid = threadIdx.x;            // 512
    __shared__ float sm[5025];
    __shared__ float red[512];
    float lmax = -3.0e38f;
    for (int idx = tid; idx < 5025; idx += 512) {
        int o = idx / 25, pos = idx % 25;
        float v = g_L[(b * 25 + pos) * 201 + o] + bias[o];
        sm[idx] = v;
        lmax = fmaxf(lmax, v);
    }
    red[tid] = lmax;
    __syncthreads();
    for (int s = 256; s > 0; s >>= 1) {
        if (tid < s) red[tid] = fmaxf(red[tid], red[tid + s]);
        __syncthreads();
    }
    float mx = red[0];
    __syncthreads();
    float lsum = 0.f;
    for (int idx = tid; idx < 5025; idx += 512) {
        float e = expf(sm[idx] - mx);
        sm[idx] = e;
        lsum += e;
    }
    red[tid] = lsum;
    __syncthreads();
    for (int s = 256; s > 0; s >>= 1) {
        if (tid < s) red[tid] += red[tid + s];
        __syncthreads();
    }
    float inv = 1.f / red[0];
    __syncthreads();
    float* s_out = out + 1608;
    for (int idx = tid; idx < 5025; idx += 512)
        s_out[b * 5025 + idx] = sm[idx] * inv;
    for (int o = tid; o < 201; o += 512) {
        float acc = 0.f;
        for (int pos = 0; pos < 25; pos++) acc += sm[o * 25 + pos];
        out[b * 201 + o] = acc * inv;
    }
}

// ---------------------------------------------------------------------------
extern "C" void kernel_launch(void* const* d_in, const int* in_sizes, int n_in,
                              void* d_out, int out_size) {
    const float* x           = (const float*)d_in[0];
    const float* conv_last_w = (const float*)d_in[3];
    const float* bn_last_g   = (const float*)d_in[4];
    const float* bn_last_b   = (const float*)d_in[5];
    const float* loc_w1      = (const float*)d_in[6];
    const float* loc_g1      = (const float*)d_in[7];
    const float* loc_b1      = (const float*)d_in[8];
    const float* loc_w2      = (const float*)d_in[9];
    const float* loc_g2      = (const float*)d_in[10];
    const float* loc_b2      = (const float*)d_in[11];
    const float* fc1_w       = (const float*)d_in[12];
    const float* fc2_w       = (const float*)d_in[13];
    const float* conv_stn_w  = (const float*)d_in[14];
    const float* conv_stn_b  = (const float*)d_in[15];
    float* out = (float*)d_out;
    float* out_theta = out + 1608 + 40200;

    cudaFuncSetAttribute(sgemm_tc, cudaFuncAttributeMaxDynamicSharedMemorySize,
                         SMEM_TC_BYTES);

    const int ELT_BLOCKS = (MM * CCH + 255) / 256;   // 1600

    // ---- backbone tail: conv_last + BN -> f ----
    im2col_x_k<<<ELT_BLOCKS, 256>>>(x);
    sgemm_tc<<<dim3(16, 2, 9), 256, SMEM_TC_BYTES>>>(conv_last_w, 2048, 2048);
    reduce_k<<<(MM * 2048 + 255) / 256, 256>>>(0, 2048, 9);
    bn_stats_k<<<2048, 64>>>();
    bn_apply_k<<<ELT_BLOCKS, 256>>>(bn_last_g, bn_last_b, 0, 0);

    // ---- localization conv1 ----
    im2col5_k<<<ELT_BLOCKS, 256>>>(0);
    sgemm_tc<<<dim3(16, 2, 9), 256, SMEM_TC_BYTES>>>(loc_w1, 2048, 2048);
    reduce_k<<<(MM * 2048 + 255) / 256, 256>>>(0, 2048, 9);
    bn_stats_k<<<2048, 64>>>();
    bn_apply_k<<<ELT_BLOCKS, 256>>>(loc_g1, loc_b1, 1, 1);

    // ---- localization conv2 ----
    im2col5_k<<<ELT_BLOCKS, 256>>>(1);
    sgemm_tc<<<dim3(16, 2, 9), 256, SMEM_TC_BYTES>>>(loc_w2, 2048, 2048);
    reduce_k<<<(MM * 2048 + 255) / 256, 256>>>(0, 2048, 9);
    bn_stats_k<<<2048, 64>>>();
    bn_apply_k<<<ELT_BLOCKS, 256>>>(loc_g2, loc_b2, 1, 1);

    // ---- fc1 (3x3 conv, 512 outputs) ----
    im2col5_k<<<ELT_BLOCKS, 256>>>(1);
    sgemm_tc<<<dim3(4, 2, 18), 256, SMEM_TC_BYTES>>>(fc1_w, 512, 1024);
    reduce_k<<<(MM * 512 + 255) / 256, 256>>>(1, 512, 18);

    // ---- fc2 + theta + grids ----
    fc2_theta_k<<<200, 128>>>(fc2_w, out_theta);

    // ---- bilinear sample -> im2col A ----
    sample_k<<<1800, 256>>>();

    // ---- conv_stn GEMM ----
    sgemm_tc<<<dim3(2, 2, 36), 256, SMEM_TC_BYTES>>>(conv_stn_w, 201, 512);
    reduce_k<<<(MM * 201 + 255) / 256, 256>>>(2, 201, 36);

    // ---- joint softmax + outputs ----
    softmax_k<<<8, 512>>>(conv_stn_b, out);
}